// round 1
// baseline (speedup 1.0000x reference)
#include <cuda_runtime.h>
#include <cstdint>

// Problem constants
#define B_   16
#define S_   626
#define D_   768
#define H_   12
#define HD_  64
#define M_   (B_*S_)          // 10016
#define BH_  (B_*H_)          // 192
#define SM1_ (S_-1)           // 625

// Scratch (device globals; no cudaMalloc allowed)
__device__ float g_q[BH_*(size_t)S_*HD_];     // [b,h,s,hd]
__device__ float g_k[BH_*(size_t)S_*HD_];
__device__ float g_v[BH_*(size_t)S_*HD_];
__device__ float g_ctx[(size_t)M_*D_];        // [b,s, h*64+hd]
__device__ float g_contrib[BH_*S_];           // raw (fixed) scores col 0

// ---------------------------------------------------------------------------
// Fused QKV projection: C[M,2304] = X @ [Wq|Wk|Wv] + bias, scattered epilogue
// 128x128 block tile, BK=8, 256 threads, 8x8 per thread. fp32 SIMT.
// ---------------------------------------------------------------------------
__global__ __launch_bounds__(256) void gemm_qkv(
    const float* __restrict__ X,
    const float* __restrict__ Wq, const float* __restrict__ bq,
    const float* __restrict__ Wk, const float* __restrict__ bk,
    const float* __restrict__ Wv, const float* __restrict__ bv)
{
    __shared__ float As[8][128];
    __shared__ float Bs[8][128];
    const int tid = threadIdx.x;
    const int m0  = blockIdx.x * 128;
    const int ng  = blockIdx.y * 128;        // 0..2303, block within a single matrix (768%128==0)
    const int mat = ng / D_;
    const int n0  = ng - mat * D_;
    const float* W    = (mat == 0) ? Wq : (mat == 1) ? Wk : Wv;
    const float* bias = (mat == 0) ? bq : (mat == 1) ? bk : bv;
    float* dst        = (mat == 0) ? g_q : (mat == 1) ? g_k : g_v;

    const int tx = tid & 15, ty = tid >> 4;
    const int arow = tid >> 1, acol = (tid & 1) * 4;
    const int brow = tid >> 5, bcol = (tid & 31) * 4;

    float acc[8][8];
    #pragma unroll
    for (int i = 0; i < 8; i++)
        #pragma unroll
        for (int j = 0; j < 8; j++) acc[i][j] = 0.f;

    const int gm = m0 + arow;
    const bool aval = (gm < M_);

    for (int k0 = 0; k0 < D_; k0 += 8) {
        float4 av = make_float4(0.f, 0.f, 0.f, 0.f);
        if (aval) av = *(const float4*)(X + (size_t)gm * D_ + k0 + acol);
        As[acol+0][arow] = av.x; As[acol+1][arow] = av.y;
        As[acol+2][arow] = av.z; As[acol+3][arow] = av.w;
        *(float4*)(&Bs[brow][bcol]) =
            *(const float4*)(W + (size_t)(k0 + brow) * D_ + n0 + bcol);
        __syncthreads();
        #pragma unroll
        for (int kk = 0; kk < 8; kk++) {
            float4 a0 = *(const float4*)&As[kk][ty*8];
            float4 a1 = *(const float4*)&As[kk][ty*8+4];
            float4 b0 = *(const float4*)&Bs[kk][tx*8];
            float4 b1 = *(const float4*)&Bs[kk][tx*8+4];
            float a[8] = {a0.x,a0.y,a0.z,a0.w,a1.x,a1.y,a1.z,a1.w};
            float b[8] = {b0.x,b0.y,b0.z,b0.w,b1.x,b1.y,b1.z,b1.w};
            #pragma unroll
            for (int i = 0; i < 8; i++)
                #pragma unroll
                for (int j = 0; j < 8; j++)
                    acc[i][j] = fmaf(a[i], b[j], acc[i][j]);
        }
        __syncthreads();
    }

    #pragma unroll
    for (int i = 0; i < 8; i++) {
        const int m = m0 + ty*8 + i;
        if (m >= M_) continue;
        const int b = m / S_, s = m - b * S_;
        #pragma unroll
        for (int j = 0; j < 8; j++) {
            const int n = n0 + tx*8 + j;
            const float v = acc[i][j] + bias[n];
            const int h = n >> 6, hd = n & 63;
            dst[(((size_t)(b*H_ + h))*S_ + s)*HD_ + hd] = v;
        }
    }
}

// ---------------------------------------------------------------------------
// Output projection: out[M,768] = g_ctx @ Wo + bo
// ---------------------------------------------------------------------------
__global__ __launch_bounds__(256) void gemm_out(
    const float* __restrict__ W, const float* __restrict__ bias,
    float* __restrict__ out)
{
    __shared__ float As[8][128];
    __shared__ float Bs[8][128];
    const int tid = threadIdx.x;
    const int m0  = blockIdx.x * 128;
    const int n0  = blockIdx.y * 128;

    const int tx = tid & 15, ty = tid >> 4;
    const int arow = tid >> 1, acol = (tid & 1) * 4;
    const int brow = tid >> 5, bcol = (tid & 31) * 4;

    float acc[8][8];
    #pragma unroll
    for (int i = 0; i < 8; i++)
        #pragma unroll
        for (int j = 0; j < 8; j++) acc[i][j] = 0.f;

    const int gm = m0 + arow;
    const bool aval = (gm < M_);

    for (int k0 = 0; k0 < D_; k0 += 8) {
        float4 av = make_float4(0.f, 0.f, 0.f, 0.f);
        if (aval) av = *(const float4*)(g_ctx + (size_t)gm * D_ + k0 + acol);
        As[acol+0][arow] = av.x; As[acol+1][arow] = av.y;
        As[acol+2][arow] = av.z; As[acol+3][arow] = av.w;
        *(float4*)(&Bs[brow][bcol]) =
            *(const float4*)(W + (size_t)(k0 + brow) * D_ + n0 + bcol);
        __syncthreads();
        #pragma unroll
        for (int kk = 0; kk < 8; kk++) {
            float4 a0 = *(const float4*)&As[kk][ty*8];
            float4 a1 = *(const float4*)&As[kk][ty*8+4];
            float4 b0 = *(const float4*)&Bs[kk][tx*8];
            float4 b1 = *(const float4*)&Bs[kk][tx*8+4];
            float a[8] = {a0.x,a0.y,a0.z,a0.w,a1.x,a1.y,a1.z,a1.w};
            float b[8] = {b0.x,b0.y,b0.z,b0.w,b1.x,b1.y,b1.z,b1.w};
            #pragma unroll
            for (int i = 0; i < 8; i++)
                #pragma unroll
                for (int j = 0; j < 8; j++)
                    acc[i][j] = fmaf(a[i], b[j], acc[i][j]);
        }
        __syncthreads();
    }

    #pragma unroll
    for (int i = 0; i < 8; i++) {
        const int m = m0 + ty*8 + i;
        if (m >= M_) continue;
        #pragma unroll
        for (int j = 0; j < 8; j++) {
            const int n = n0 + tx*8 + j;
            out[(size_t)m * D_ + n] = acc[i][j] + bias[n];
        }
    }
}

// ---------------------------------------------------------------------------
// Scores: per (b,h): scores[626,626] = (q @ k^T) * 0.125, written to d_out probs
// 64x64 tile, 256 threads, 4x4 per thread, K=64 in one shot.
// ---------------------------------------------------------------------------
__global__ __launch_bounds__(256) void scores_kernel(float* __restrict__ probs)
{
    const int bh = blockIdx.z;
    const int m0 = blockIdx.y * 64;
    const int n0 = blockIdx.x * 64;
    __shared__ float Qs[64][68];  // [d][m], pad 68 keeps 16B align
    __shared__ float Ks[64][68];  // [d][n]
    const int tid = threadIdx.x;
    const int tx = tid & 15, ty = tid >> 4;

    const float* qb = g_q + (size_t)bh * S_ * HD_;
    const float* kb = g_k + (size_t)bh * S_ * HD_;

    #pragma unroll
    for (int it = 0; it < 4; it++) {
        const int slot = tid + it * 256;
        const int row = slot >> 4;
        const int c4  = (slot & 15) * 4;
        float4 qv = make_float4(0.f,0.f,0.f,0.f);
        float4 kv = make_float4(0.f,0.f,0.f,0.f);
        if (m0 + row < S_) qv = *(const float4*)(qb + (size_t)(m0+row)*HD_ + c4);
        if (n0 + row < S_) kv = *(const float4*)(kb + (size_t)(n0+row)*HD_ + c4);
        Qs[c4+0][row]=qv.x; Qs[c4+1][row]=qv.y; Qs[c4+2][row]=qv.z; Qs[c4+3][row]=qv.w;
        Ks[c4+0][row]=kv.x; Ks[c4+1][row]=kv.y; Ks[c4+2][row]=kv.z; Ks[c4+3][row]=kv.w;
    }
    __syncthreads();

    float acc[4][4];
    #pragma unroll
    for (int i = 0; i < 4; i++)
        #pragma unroll
        for (int j = 0; j < 4; j++) acc[i][j] = 0.f;

    #pragma unroll
    for (int kk = 0; kk < 64; kk++) {
        const float4 a = *(const float4*)&Qs[kk][ty*4];
        const float4 b = *(const float4*)&Ks[kk][tx*4];
        const float av[4] = {a.x, a.y, a.z, a.w};
        const float bv[4] = {b.x, b.y, b.z, b.w};
        #pragma unroll
        for (int i = 0; i < 4; i++)
            #pragma unroll
            for (int j = 0; j < 4; j++)
                acc[i][j] = fmaf(av[i], bv[j], acc[i][j]);
    }

    #pragma unroll
    for (int i = 0; i < 4; i++) {
        const int m = m0 + ty*4 + i;
        if (m >= S_) continue;
        #pragma unroll
        for (int j = 0; j < 4; j++) {
            const int n = n0 + tx*4 + j;
            if (n >= S_) continue;
            probs[((size_t)bh * S_ + m) * S_ + n] = acc[i][j] * 0.125f;
        }
    }
}

// ---------------------------------------------------------------------------
// Row softmax, in place on the probs region. Handles:
//  - q==0 row mask fix: row0 += max(row0)*0.25 where mask626==0 (k=0 always)
//  - capture of fixed scores column 0 into g_contrib
// One block per (bh, q) row.
// ---------------------------------------------------------------------------
__global__ __launch_bounds__(256) void softmax_kernel(
    float* __restrict__ probs, const int* __restrict__ mask)
{
    const int row = blockIdx.x;            // bh*S + q
    const int bh  = row / S_;
    const int q   = row - bh * S_;
    const int b   = bh / H_;
    float* p = probs + (size_t)row * S_;

    __shared__ float buf[S_];
    __shared__ float red[8];
    const int tid = threadIdx.x;

    for (int i = tid; i < S_; i += 256) buf[i] = p[i];
    __syncthreads();

    // block max
    float m = -3.4e38f;
    for (int i = tid; i < S_; i += 256) m = fmaxf(m, buf[i]);
    #pragma unroll
    for (int o = 16; o; o >>= 1) m = fmaxf(m, __shfl_xor_sync(0xffffffffu, m, o));
    if ((tid & 31) == 0) red[tid >> 5] = m;
    __syncthreads();
    if (tid == 0) {
        float mm = red[0];
        #pragma unroll
        for (int w = 1; w < 8; w++) mm = fmaxf(mm, red[w]);
        red[0] = mm;
    }
    __syncthreads();
    m = red[0];
    __syncthreads();   // everyone has read red[0] before any reuse

    if (q == 0) {
        const float add = m * 0.25f;   // max of ORIGINAL row
        for (int i = tid; i < S_; i += 256) {
            const int mk = (i == 0) ? 0 : mask[b * SM1_ + i - 1];
            if (mk == 0) buf[i] += add;
        }
        __syncthreads();
        // recompute max of fixed row
        float m2 = -3.4e38f;
        for (int i = tid; i < S_; i += 256) m2 = fmaxf(m2, buf[i]);
        #pragma unroll
        for (int o = 16; o; o >>= 1) m2 = fmaxf(m2, __shfl_xor_sync(0xffffffffu, m2, o));
        if ((tid & 31) == 0) red[tid >> 5] = m2;
        __syncthreads();
        if (tid == 0) {
            float mm = red[0];
            #pragma unroll
            for (int w = 1; w < 8; w++) mm = fmaxf(mm, red[w]);
            red[0] = mm;
        }
        __syncthreads();
        m = red[0];
        __syncthreads();
    }

    // capture (fixed) score at k==0 for the contribution softmax
    if (tid == 0) g_contrib[row] = buf[0];

    // exp + sum
    float s = 0.f;
    for (int i = tid; i < S_; i += 256) {
        const float e = expf(buf[i] - m);
        buf[i] = e;
        s += e;
    }
    #pragma unroll
    for (int o = 16; o; o >>= 1) s += __shfl_xor_sync(0xffffffffu, s, o);
    if ((tid & 31) == 0) red[tid >> 5] = s;
    __syncthreads();
    if (tid == 0) {
        float ss = 0.f;
        #pragma unroll
        for (int w = 0; w < 8; w++) ss += red[w];
        red[0] = ss;
    }
    __syncthreads();
    const float inv = 1.0f / red[0];
    for (int i = tid; i < S_; i += 256) p[i] = buf[i] * inv;
}

// ---------------------------------------------------------------------------
// Contribution: softmax over q of g_contrib[bh, :], one block per (b,h)
// ---------------------------------------------------------------------------
__global__ __launch_bounds__(256) void contrib_kernel(float* __restrict__ out)
{
    const int bh = blockIdx.x;
    const float* src = g_contrib + (size_t)bh * S_;
    __shared__ float red[8];
    const int tid = threadIdx.x;

    float m = -3.4e38f;
    for (int i = tid; i < S_; i += 256) m = fmaxf(m, src[i]);
    #pragma unroll
    for (int o = 16; o; o >>= 1) m = fmaxf(m, __shfl_xor_sync(0xffffffffu, m, o));
    if ((tid & 31) == 0) red[tid >> 5] = m;
    __syncthreads();
    if (tid == 0) {
        float mm = red[0];
        #pragma unroll
        for (int w = 1; w < 8; w++) mm = fmaxf(mm, red[w]);
        red[0] = mm;
    }
    __syncthreads();
    m = red[0];
    __syncthreads();

    float s = 0.f;
    for (int i = tid; i < S_; i += 256) s += expf(src[i] - m);
    #pragma unroll
    for (int o = 16; o; o >>= 1) s += __shfl_xor_sync(0xffffffffu, s, o);
    if ((tid & 31) == 0) red[tid >> 5] = s;
    __syncthreads();
    if (tid == 0) {
        float ss = 0.f;
        #pragma unroll
        for (int w = 0; w < 8; w++) ss += red[w];
        red[0] = ss;
    }
    __syncthreads();
    const float inv = 1.0f / red[0];
    for (int i = tid; i < S_; i += 256)
        out[(size_t)bh * S_ + i] = expf(src[i] - m) * inv;
}

// ---------------------------------------------------------------------------
// Context: per (b,h): ctx[626,64] = probs[626,626] @ v[626,64]
// 64(rows) x 64(cols) per block, BK=64 loop. P loads are scalar (626 rows
// are not 16B-aligned), V loads are float4.
// ---------------------------------------------------------------------------
__global__ __launch_bounds__(256) void ctx_kernel(const float* __restrict__ probs)
{
    const int bh = blockIdx.y;
    const int m0 = blockIdx.x * 64;
    __shared__ float Ps[64][68];  // [k][m] (transposed)
    __shared__ float Vs[64][68];  // [k][n]
    const int tid = threadIdx.x;
    const int tx = tid & 15, ty = tid >> 4;

    const float* pb = probs + (size_t)bh * S_ * S_;
    const float* vb = g_v   + (size_t)bh * S_ * HD_;

    float acc[4][4];
    #pragma unroll
    for (int i = 0; i < 4; i++)
        #pragma unroll
        for (int j = 0; j < 4; j++) acc[i][j] = 0.f;

    for (int k0 = 0; k0 < S_; k0 += 64) {
        #pragma unroll
        for (int it = 0; it < 4; it++) {
            const int slot = tid + it * 256;
            const int row = slot >> 4;          // 0..63
            const int c4  = (slot & 15) * 4;
            // P tile: logical [m=m0+row][k=k0+c4..c4+3] -> Ps[k][m] (scalar, unaligned rows)
            float pv0 = 0.f, pv1 = 0.f, pv2 = 0.f, pv3 = 0.f;
            if (m0 + row < S_) {
                const size_t base = (size_t)(m0 + row) * S_ + k0 + c4;
                if (k0 + c4 + 0 < S_) pv0 = pb[base + 0];
                if (k0 + c4 + 1 < S_) pv1 = pb[base + 1];
                if (k0 + c4 + 2 < S_) pv2 = pb[base + 2];
                if (k0 + c4 + 3 < S_) pv3 = pb[base + 3];
            }
            Ps[c4+0][row] = pv0; Ps[c4+1][row] = pv1;
            Ps[c4+2][row] = pv2; Ps[c4+3][row] = pv3;
            // V tile: [k=k0+row][n=c4..c4+3]
            float4 vv = make_float4(0.f,0.f,0.f,0.f);
            if (k0 + row < S_) vv = *(const float4*)(vb + (size_t)(k0+row)*HD_ + c4);
            *(float4*)&Vs[row][c4] = vv;
        }
        __syncthreads();
        #pragma unroll
        for (int kk = 0; kk < 64; kk++) {
            const float4 a = *(const float4*)&Ps[kk][ty*4];
            const float4 b = *(const float4*)&Vs[kk][tx*4];
            const float av[4] = {a.x, a.y, a.z, a.w};
            const float bv4[4] = {b.x, b.y, b.z, b.w};
            #pragma unroll
            for (int i = 0; i < 4; i++)
                #pragma unroll
                for (int j = 0; j < 4; j++)
                    acc[i][j] = fmaf(av[i], bv4[j], acc[i][j]);
        }
        __syncthreads();
    }

    const int b = bh / H_, h = bh - b * H_;
    #pragma unroll
    for (int i = 0; i < 4; i++) {
        const int m = m0 + ty*4 + i;
        if (m >= S_) continue;
        #pragma unroll
        for (int j = 0; j < 4; j++) {
            const int n = tx*4 + j;
            g_ctx[((size_t)(b*S_ + m)) * D_ + h*HD_ + n] = acc[i][j];
        }
    }
}

// ---------------------------------------------------------------------------
// Launch
// ---------------------------------------------------------------------------
extern "C" void kernel_launch(void* const* d_in, const int* in_sizes, int n_in,
                              void* d_out, int out_size)
{
    const float* hs = (const float*)d_in[0];
    const int*  mask = (const int*) d_in[1];
    const float* Wq = (const float*)d_in[2];
    const float* bq = (const float*)d_in[3];
    const float* Wk = (const float*)d_in[4];
    const float* bk = (const float*)d_in[5];
    const float* Wv = (const float*)d_in[6];
    const float* bv = (const float*)d_in[7];
    const float* Wo = (const float*)d_in[8];
    const float* bo = (const float*)d_in[9];

    float* out     = (float*)d_out;
    float* att_out = out;                                       // [B,S,D]
    float* probs   = out + (size_t)M_ * D_;                     // [B,H,S,S]
    float* contrib = probs + (size_t)BH_ * S_ * S_;             // [B,H,S]

    // 1. QKV projections
    gemm_qkv<<<dim3(79, 18), 256>>>(hs, Wq, bq, Wk, bk, Wv, bv);
    // 2. Raw scores (scaled) -> probs region of d_out
    scores_kernel<<<dim3(10, 10, 192), 256>>>(probs);
    // 3. Row-0 fix + in-place softmax over k + contribution capture
    softmax_kernel<<<BH_ * S_, 256>>>(probs, mask);
    // 4. Contribution softmax over q
    contrib_kernel<<<BH_, 256>>>(contrib);
    // 5. ctx = probs @ V
    ctx_kernel<<<dim3(10, 192), 256>>>(probs);
    // 6. attention_output = ctx @ Wo + bo
    gemm_out<<<dim3(79, 6), 256>>>(Wo, bo, att_out);
}

// round 2
// speedup vs baseline: 2.0845x; 2.0845x over previous
#include <cuda_runtime.h>
#include <cstdint>

// Problem constants
#define B_   16
#define S_   626
#define D_   768
#define H_   12
#define HD_  64
#define M_   (B_*S_)          // 10016
#define BH_  (B_*H_)          // 192
#define SM1_ (S_-1)           // 625

// Scratch (device globals; no cudaMalloc allowed)
__device__ float g_q[BH_*(size_t)S_*HD_];     // [b,h,s,hd]
__device__ float g_k[BH_*(size_t)S_*HD_];
__device__ float g_v[BH_*(size_t)S_*HD_];
__device__ float g_ctx[(size_t)M_*D_];        // [b,s, h*64+hd]
__device__ float g_contrib[BH_*S_];           // raw (fixed) scores col 0

// ---------------------------------------------------------------------------
// tf32 helpers
// ---------------------------------------------------------------------------
__device__ __forceinline__ uint32_t f2t(float x) {
    uint32_t r;
    asm("cvt.rna.tf32.f32 %0, %1;" : "=r"(r) : "f"(x));
    return r;
}

__device__ __forceinline__ void mma_tf32(float c[4],
    uint32_t a0, uint32_t a1, uint32_t a2, uint32_t a3,
    uint32_t b0, uint32_t b1)
{
    asm volatile(
        "mma.sync.aligned.m16n8k8.row.col.f32.tf32.tf32.f32 "
        "{%0,%1,%2,%3}, {%4,%5,%6,%7}, {%8,%9}, {%0,%1,%2,%3};"
        : "+f"(c[0]), "+f"(c[1]), "+f"(c[2]), "+f"(c[3])
        : "r"(a0), "r"(a1), "r"(a2), "r"(a3), "r"(b0), "r"(b1));
}

// ---------------------------------------------------------------------------
// Fused QKV projection (tf32 MMA): C[M,2304] = X @ [Wq|Wk|Wv] + bias,
// scattered epilogue to [b,h,s,hd]. 128x128 tile, BK=16, 256 threads.
// ---------------------------------------------------------------------------
__global__ __launch_bounds__(256) void gemm_qkv(
    const float* __restrict__ X,
    const float* __restrict__ Wq, const float* __restrict__ bq,
    const float* __restrict__ Wk, const float* __restrict__ bk,
    const float* __restrict__ Wv, const float* __restrict__ bv)
{
    __shared__ uint32_t As[128][20];   // [m][k], pad 20 -> conflict-free frag LDS
    __shared__ uint32_t Bs[16][136];   // [k][n]
    const int tid = threadIdx.x;
    const int m0  = blockIdx.x * 128;
    const int ng  = blockIdx.y * 128;
    const int mat = ng / D_;
    const int n0  = ng - mat * D_;
    const float* W    = (mat == 0) ? Wq : (mat == 1) ? Wk : Wv;
    const float* bias = (mat == 0) ? bq : (mat == 1) ? bk : bv;
    float* dst        = (mat == 0) ? g_q : (mat == 1) ? g_k : g_v;

    const int wid = tid >> 5, lane = tid & 31;
    const int gid = lane >> 2, tk = lane & 3;
    const int wm = (wid & 1) * 64;   // 2 warps along m (64 rows each)
    const int wn = (wid >> 1) * 32;  // 4 warps along n (32 cols each)

    float acc[4][4][4];
    #pragma unroll
    for (int mi = 0; mi < 4; mi++)
        #pragma unroll
        for (int ni = 0; ni < 4; ni++)
            #pragma unroll
            for (int r = 0; r < 4; r++) acc[mi][ni][r] = 0.f;

    for (int k0 = 0; k0 < D_; k0 += 16) {
        #pragma unroll
        for (int i = 0; i < 2; i++) {
            const int idx = tid + i * 256;
            const int row = idx >> 2, c4 = (idx & 3) << 2;
            float4 v = make_float4(0.f, 0.f, 0.f, 0.f);
            if (m0 + row < M_)
                v = *(const float4*)(X + (size_t)(m0 + row) * D_ + k0 + c4);
            uint4 t;
            t.x = f2t(v.x); t.y = f2t(v.y); t.z = f2t(v.z); t.w = f2t(v.w);
            *(uint4*)&As[row][c4] = t;
        }
        #pragma unroll
        for (int i = 0; i < 2; i++) {
            const int idx = tid + i * 256;
            const int kr = idx >> 5, c4 = (idx & 31) << 2;
            float4 v = *(const float4*)(W + (size_t)(k0 + kr) * D_ + n0 + c4);
            uint4 t;
            t.x = f2t(v.x); t.y = f2t(v.y); t.z = f2t(v.z); t.w = f2t(v.w);
            *(uint4*)&Bs[kr][c4] = t;
        }
        __syncthreads();
        #pragma unroll
        for (int ks = 0; ks < 16; ks += 8) {
            uint32_t bf[4][2];
            #pragma unroll
            for (int ni = 0; ni < 4; ni++) {
                bf[ni][0] = Bs[ks + tk    ][wn + ni * 8 + gid];
                bf[ni][1] = Bs[ks + tk + 4][wn + ni * 8 + gid];
            }
            #pragma unroll
            for (int mi = 0; mi < 4; mi++) {
                const int am = wm + mi * 16;
                const uint32_t a0 = As[am + gid    ][ks + tk];
                const uint32_t a1 = As[am + gid + 8][ks + tk];
                const uint32_t a2 = As[am + gid    ][ks + tk + 4];
                const uint32_t a3 = As[am + gid + 8][ks + tk + 4];
                #pragma unroll
                for (int ni = 0; ni < 4; ni++)
                    mma_tf32(acc[mi][ni], a0, a1, a2, a3, bf[ni][0], bf[ni][1]);
            }
        }
        __syncthreads();
    }

    #pragma unroll
    for (int mi = 0; mi < 4; mi++) {
        #pragma unroll
        for (int ni = 0; ni < 4; ni++) {
            const int col = n0 + wn + ni * 8 + 2 * tk;   // within this matrix
            const int h = col >> 6, hd = col & 63;
            const float b0v = bias[col], b1v = bias[col + 1];
            const int r0 = m0 + wm + mi * 16 + gid;
            const int r1 = r0 + 8;
            if (r0 < M_) {
                const int b = r0 / S_, s = r0 - b * S_;
                float2 o = make_float2(acc[mi][ni][0] + b0v, acc[mi][ni][1] + b1v);
                *(float2*)(dst + (((size_t)(b * H_ + h)) * S_ + s) * HD_ + hd) = o;
            }
            if (r1 < M_) {
                const int b = r1 / S_, s = r1 - b * S_;
                float2 o = make_float2(acc[mi][ni][2] + b0v, acc[mi][ni][3] + b1v);
                *(float2*)(dst + (((size_t)(b * H_ + h)) * S_ + s) * HD_ + hd) = o;
            }
        }
    }
}

// ---------------------------------------------------------------------------
// Output projection (tf32 MMA): out[M,768] = g_ctx @ Wo + bo
// ---------------------------------------------------------------------------
__global__ __launch_bounds__(256) void gemm_out(
    const float* __restrict__ W, const float* __restrict__ bias,
    float* __restrict__ out)
{
    __shared__ uint32_t As[128][20];
    __shared__ uint32_t Bs[16][136];
    const int tid = threadIdx.x;
    const int m0  = blockIdx.x * 128;
    const int n0  = blockIdx.y * 128;

    const int wid = tid >> 5, lane = tid & 31;
    const int gid = lane >> 2, tk = lane & 3;
    const int wm = (wid & 1) * 64;
    const int wn = (wid >> 1) * 32;

    float acc[4][4][4];
    #pragma unroll
    for (int mi = 0; mi < 4; mi++)
        #pragma unroll
        for (int ni = 0; ni < 4; ni++)
            #pragma unroll
            for (int r = 0; r < 4; r++) acc[mi][ni][r] = 0.f;

    for (int k0 = 0; k0 < D_; k0 += 16) {
        #pragma unroll
        for (int i = 0; i < 2; i++) {
            const int idx = tid + i * 256;
            const int row = idx >> 2, c4 = (idx & 3) << 2;
            float4 v = make_float4(0.f, 0.f, 0.f, 0.f);
            if (m0 + row < M_)
                v = *(const float4*)(g_ctx + (size_t)(m0 + row) * D_ + k0 + c4);
            uint4 t;
            t.x = f2t(v.x); t.y = f2t(v.y); t.z = f2t(v.z); t.w = f2t(v.w);
            *(uint4*)&As[row][c4] = t;
        }
        #pragma unroll
        for (int i = 0; i < 2; i++) {
            const int idx = tid + i * 256;
            const int kr = idx >> 5, c4 = (idx & 31) << 2;
            float4 v = *(const float4*)(W + (size_t)(k0 + kr) * D_ + n0 + c4);
            uint4 t;
            t.x = f2t(v.x); t.y = f2t(v.y); t.z = f2t(v.z); t.w = f2t(v.w);
            *(uint4*)&Bs[kr][c4] = t;
        }
        __syncthreads();
        #pragma unroll
        for (int ks = 0; ks < 16; ks += 8) {
            uint32_t bf[4][2];
            #pragma unroll
            for (int ni = 0; ni < 4; ni++) {
                bf[ni][0] = Bs[ks + tk    ][wn + ni * 8 + gid];
                bf[ni][1] = Bs[ks + tk + 4][wn + ni * 8 + gid];
            }
            #pragma unroll
            for (int mi = 0; mi < 4; mi++) {
                const int am = wm + mi * 16;
                const uint32_t a0 = As[am + gid    ][ks + tk];
                const uint32_t a1 = As[am + gid + 8][ks + tk];
                const uint32_t a2 = As[am + gid    ][ks + tk + 4];
                const uint32_t a3 = As[am + gid + 8][ks + tk + 4];
                #pragma unroll
                for (int ni = 0; ni < 4; ni++)
                    mma_tf32(acc[mi][ni], a0, a1, a2, a3, bf[ni][0], bf[ni][1]);
            }
        }
        __syncthreads();
    }

    #pragma unroll
    for (int mi = 0; mi < 4; mi++) {
        #pragma unroll
        for (int ni = 0; ni < 4; ni++) {
            const int col = n0 + wn + ni * 8 + 2 * tk;
            const float b0v = bias[col], b1v = bias[col + 1];
            const int r0 = m0 + wm + mi * 16 + gid;
            const int r1 = r0 + 8;
            if (r0 < M_)
                *(float2*)(out + (size_t)r0 * D_ + col) =
                    make_float2(acc[mi][ni][0] + b0v, acc[mi][ni][1] + b1v);
            if (r1 < M_)
                *(float2*)(out + (size_t)r1 * D_ + col) =
                    make_float2(acc[mi][ni][2] + b0v, acc[mi][ni][3] + b1v);
        }
    }
}

// ---------------------------------------------------------------------------
// Scores (tf32 MMA): per (b,h): scores[626,626] = (q @ k^T) * 0.125 -> probs
// 128x128 tile, K=64 (4 x BK16). B tile kept [n][k] (K matrix natural rows).
// ---------------------------------------------------------------------------
__global__ __launch_bounds__(256) void scores_kernel(float* __restrict__ probs)
{
    __shared__ uint32_t As[128][20];   // Q: [m][k]
    __shared__ uint32_t Ns[128][20];   // K: [n][k]
    const int bh = blockIdx.z;
    const int m0 = blockIdx.y * 128;
    const int n0 = blockIdx.x * 128;
    const int tid = threadIdx.x;

    const int wid = tid >> 5, lane = tid & 31;
    const int gid = lane >> 2, tk = lane & 3;
    const int wm = (wid & 1) * 64;
    const int wn = (wid >> 1) * 32;

    const float* qb = g_q + (size_t)bh * S_ * HD_;
    const float* kb = g_k + (size_t)bh * S_ * HD_;

    float acc[4][4][4];
    #pragma unroll
    for (int mi = 0; mi < 4; mi++)
        #pragma unroll
        for (int ni = 0; ni < 4; ni++)
            #pragma unroll
            for (int r = 0; r < 4; r++) acc[mi][ni][r] = 0.f;

    #pragma unroll
    for (int k0 = 0; k0 < HD_; k0 += 16) {
        #pragma unroll
        for (int i = 0; i < 2; i++) {
            const int idx = tid + i * 256;
            const int row = idx >> 2, c4 = (idx & 3) << 2;
            float4 qv = make_float4(0.f, 0.f, 0.f, 0.f);
            float4 kv = make_float4(0.f, 0.f, 0.f, 0.f);
            if (m0 + row < S_) qv = *(const float4*)(qb + (size_t)(m0 + row) * HD_ + k0 + c4);
            if (n0 + row < S_) kv = *(const float4*)(kb + (size_t)(n0 + row) * HD_ + k0 + c4);
            uint4 tq, tn;
            tq.x = f2t(qv.x); tq.y = f2t(qv.y); tq.z = f2t(qv.z); tq.w = f2t(qv.w);
            tn.x = f2t(kv.x); tn.y = f2t(kv.y); tn.z = f2t(kv.z); tn.w = f2t(kv.w);
            *(uint4*)&As[row][c4] = tq;
            *(uint4*)&Ns[row][c4] = tn;
        }
        __syncthreads();
        #pragma unroll
        for (int ks = 0; ks < 16; ks += 8) {
            uint32_t bf[4][2];
            #pragma unroll
            for (int ni = 0; ni < 4; ni++) {
                const int nb = wn + ni * 8 + gid;
                bf[ni][0] = Ns[nb][ks + tk];
                bf[ni][1] = Ns[nb][ks + tk + 4];
            }
            #pragma unroll
            for (int mi = 0; mi < 4; mi++) {
                const int am = wm + mi * 16;
                const uint32_t a0 = As[am + gid    ][ks + tk];
                const uint32_t a1 = As[am + gid + 8][ks + tk];
                const uint32_t a2 = As[am + gid    ][ks + tk + 4];
                const uint32_t a3 = As[am + gid + 8][ks + tk + 4];
                #pragma unroll
                for (int ni = 0; ni < 4; ni++)
                    mma_tf32(acc[mi][ni], a0, a1, a2, a3, bf[ni][0], bf[ni][1]);
            }
        }
        __syncthreads();
    }

    float* pb = probs + (size_t)bh * S_ * S_;
    #pragma unroll
    for (int mi = 0; mi < 4; mi++) {
        #pragma unroll
        for (int ni = 0; ni < 4; ni++) {
            const int col = n0 + wn + ni * 8 + 2 * tk;
            if (col >= S_) continue;      // col even; col+1 valid iff col valid
            const int r0 = m0 + wm + mi * 16 + gid;
            const int r1 = r0 + 8;
            if (r0 < S_)
                *(float2*)(pb + (size_t)r0 * S_ + col) =
                    make_float2(acc[mi][ni][0] * 0.125f, acc[mi][ni][1] * 0.125f);
            if (r1 < S_)
                *(float2*)(pb + (size_t)r1 * S_ + col) =
                    make_float2(acc[mi][ni][2] * 0.125f, acc[mi][ni][3] * 0.125f);
        }
    }
}

// ---------------------------------------------------------------------------
// Row softmax (in place on probs). Row-0 mask fix + contribution capture.
// ---------------------------------------------------------------------------
__global__ __launch_bounds__(256) void softmax_kernel(
    float* __restrict__ probs, const int* __restrict__ mask)
{
    const int row = blockIdx.x;            // bh*S + q
    const int bh  = row / S_;
    const int q   = row - bh * S_;
    const int b   = bh / H_;
    float* p = probs + (size_t)row * S_;

    __shared__ float buf[S_];
    __shared__ float red[8];
    const int tid = threadIdx.x;

    for (int i = tid; i < S_; i += 256) buf[i] = p[i];
    __syncthreads();

    float m = -3.4e38f;
    for (int i = tid; i < S_; i += 256) m = fmaxf(m, buf[i]);
    #pragma unroll
    for (int o = 16; o; o >>= 1) m = fmaxf(m, __shfl_xor_sync(0xffffffffu, m, o));
    if ((tid & 31) == 0) red[tid >> 5] = m;
    __syncthreads();
    if (tid == 0) {
        float mm = red[0];
        #pragma unroll
        for (int w = 1; w < 8; w++) mm = fmaxf(mm, red[w]);
        red[0] = mm;
    }
    __syncthreads();
    m = red[0];
    __syncthreads();

    if (q == 0) {
        const float add = m * 0.25f;
        for (int i = tid; i < S_; i += 256) {
            const int mk = (i == 0) ? 0 : mask[b * SM1_ + i - 1];
            if (mk == 0) buf[i] += add;
        }
        __syncthreads();
        float m2 = -3.4e38f;
        for (int i = tid; i < S_; i += 256) m2 = fmaxf(m2, buf[i]);
        #pragma unroll
        for (int o = 16; o; o >>= 1) m2 = fmaxf(m2, __shfl_xor_sync(0xffffffffu, m2, o));
        if ((tid & 31) == 0) red[tid >> 5] = m2;
        __syncthreads();
        if (tid == 0) {
            float mm = red[0];
            #pragma unroll
            for (int w = 1; w < 8; w++) mm = fmaxf(mm, red[w]);
            red[0] = mm;
        }
        __syncthreads();
        m = red[0];
        __syncthreads();
    }

    if (tid == 0) g_contrib[row] = buf[0];

    float s = 0.f;
    for (int i = tid; i < S_; i += 256) {
        const float e = expf(buf[i] - m);
        buf[i] = e;
        s += e;
    }
    #pragma unroll
    for (int o = 16; o; o >>= 1) s += __shfl_xor_sync(0xffffffffu, s, o);
    if ((tid & 31) == 0) red[tid >> 5] = s;
    __syncthreads();
    if (tid == 0) {
        float ss = 0.f;
        #pragma unroll
        for (int w = 0; w < 8; w++) ss += red[w];
        red[0] = ss;
    }
    __syncthreads();
    const float inv = 1.0f / red[0];
    for (int i = tid; i < S_; i += 256) p[i] = buf[i] * inv;
}

// ---------------------------------------------------------------------------
// Contribution: softmax over q of g_contrib[bh, :]
// ---------------------------------------------------------------------------
__global__ __launch_bounds__(256) void contrib_kernel(float* __restrict__ out)
{
    const int bh = blockIdx.x;
    const float* src = g_contrib + (size_t)bh * S_;
    __shared__ float red[8];
    const int tid = threadIdx.x;

    float m = -3.4e38f;
    for (int i = tid; i < S_; i += 256) m = fmaxf(m, src[i]);
    #pragma unroll
    for (int o = 16; o; o >>= 1) m = fmaxf(m, __shfl_xor_sync(0xffffffffu, m, o));
    if ((tid & 31) == 0) red[tid >> 5] = m;
    __syncthreads();
    if (tid == 0) {
        float mm = red[0];
        #pragma unroll
        for (int w = 1; w < 8; w++) mm = fmaxf(mm, red[w]);
        red[0] = mm;
    }
    __syncthreads();
    m = red[0];
    __syncthreads();

    float s = 0.f;
    for (int i = tid; i < S_; i += 256) s += expf(src[i] - m);
    #pragma unroll
    for (int o = 16; o; o >>= 1) s += __shfl_xor_sync(0xffffffffu, s, o);
    if ((tid & 31) == 0) red[tid >> 5] = s;
    __syncthreads();
    if (tid == 0) {
        float ss = 0.f;
        #pragma unroll
        for (int w = 0; w < 8; w++) ss += red[w];
        red[0] = ss;
    }
    __syncthreads();
    const float inv = 1.0f / red[0];
    for (int i = tid; i < S_; i += 256)
        out[(size_t)bh * S_ + i] = expf(src[i] - m) * inv;
}

// ---------------------------------------------------------------------------
// Context (tf32 MMA): per (b,h): ctx[626,64] = probs[626,626] @ v[626,64]
// 128x64 tile, BK=16, K=626 (40 iters, zero-filled tail).
// ---------------------------------------------------------------------------
__global__ __launch_bounds__(256) void ctx_kernel(const float* __restrict__ probs)
{
    __shared__ uint32_t As[128][20];   // P: [m][k]
    __shared__ uint32_t Bs[16][72];    // V: [k][n]
    const int bh = blockIdx.y;
    const int m0 = blockIdx.x * 128;
    const int tid = threadIdx.x;

    const int wid = tid >> 5, lane = tid & 31;
    const int gid = lane >> 2, tk = lane & 3;
    const int wm = (wid & 3) * 32;     // 4 warps along m (32 rows each)
    const int wn = (wid >> 2) * 32;    // 2 warps along n (32 cols each)

    const float* pb = probs + (size_t)bh * S_ * S_;
    const float* vb = g_v   + (size_t)bh * S_ * HD_;

    float acc[2][4][4];
    #pragma unroll
    for (int mi = 0; mi < 2; mi++)
        #pragma unroll
        for (int ni = 0; ni < 4; ni++)
            #pragma unroll
            for (int r = 0; r < 4; r++) acc[mi][ni][r] = 0.f;

    for (int k0 = 0; k0 < S_; k0 += 16) {
        // A (P) tile: scalar loads (rows unaligned: stride 626 floats)
        #pragma unroll
        for (int i = 0; i < 2; i++) {
            const int idx = tid + i * 256;
            const int row = idx >> 2, c4 = (idx & 3) << 2;
            float v0 = 0.f, v1 = 0.f, v2 = 0.f, v3 = 0.f;
            if (m0 + row < S_) {
                const size_t base = (size_t)(m0 + row) * S_ + k0 + c4;
                if (k0 + c4 + 0 < S_) v0 = pb[base + 0];
                if (k0 + c4 + 1 < S_) v1 = pb[base + 1];
                if (k0 + c4 + 2 < S_) v2 = pb[base + 2];
                if (k0 + c4 + 3 < S_) v3 = pb[base + 3];
            }
            As[row][c4 + 0] = f2t(v0);
            As[row][c4 + 1] = f2t(v1);
            As[row][c4 + 2] = f2t(v2);
            As[row][c4 + 3] = f2t(v3);
        }
        // B (V) tile: [16k][64n]
        {
            const int kr = tid >> 4, c4 = (tid & 15) << 2;
            float4 v = make_float4(0.f, 0.f, 0.f, 0.f);
            if (k0 + kr < S_)
                v = *(const float4*)(vb + (size_t)(k0 + kr) * HD_ + c4);
            uint4 t;
            t.x = f2t(v.x); t.y = f2t(v.y); t.z = f2t(v.z); t.w = f2t(v.w);
            *(uint4*)&Bs[kr][c4] = t;
        }
        __syncthreads();
        #pragma unroll
        for (int ks = 0; ks < 16; ks += 8) {
            uint32_t bf[4][2];
            #pragma unroll
            for (int ni = 0; ni < 4; ni++) {
                bf[ni][0] = Bs[ks + tk    ][wn + ni * 8 + gid];
                bf[ni][1] = Bs[ks + tk + 4][wn + ni * 8 + gid];
            }
            #pragma unroll
            for (int mi = 0; mi < 2; mi++) {
                const int am = wm + mi * 16;
                const uint32_t a0 = As[am + gid    ][ks + tk];
                const uint32_t a1 = As[am + gid + 8][ks + tk];
                const uint32_t a2 = As[am + gid    ][ks + tk + 4];
                const uint32_t a3 = As[am + gid + 8][ks + tk + 4];
                #pragma unroll
                for (int ni = 0; ni < 4; ni++)
                    mma_tf32(acc[mi][ni], a0, a1, a2, a3, bf[ni][0], bf[ni][1]);
            }
        }
        __syncthreads();
    }

    const int b = bh / H_, h = bh - b * H_;
    #pragma unroll
    for (int mi = 0; mi < 2; mi++) {
        #pragma unroll
        for (int ni = 0; ni < 4; ni++) {
            const int col = wn + ni * 8 + 2 * tk;   // 0..62
            const int r0 = m0 + wm + mi * 16 + gid;
            const int r1 = r0 + 8;
            if (r0 < S_)
                *(float2*)(g_ctx + ((size_t)(b * S_ + r0)) * D_ + h * HD_ + col) =
                    make_float2(acc[mi][ni][0], acc[mi][ni][1]);
            if (r1 < S_)
                *(float2*)(g_ctx + ((size_t)(b * S_ + r1)) * D_ + h * HD_ + col) =
                    make_float2(acc[mi][ni][2], acc[mi][ni][3]);
        }
    }
}

// ---------------------------------------------------------------------------
// Launch
// ---------------------------------------------------------------------------
extern "C" void kernel_launch(void* const* d_in, const int* in_sizes, int n_in,
                              void* d_out, int out_size)
{
    const float* hs = (const float*)d_in[0];
    const int*  mask = (const int*) d_in[1];
    const float* Wq = (const float*)d_in[2];
    const float* bq = (const float*)d_in[3];
    const float* Wk = (const float*)d_in[4];
    const float* bk = (const float*)d_in[5];
    const float* Wv = (const float*)d_in[6];
    const float* bv = (const float*)d_in[7];
    const float* Wo = (const float*)d_in[8];
    const float* bo = (const float*)d_in[9];

    float* out     = (float*)d_out;
    float* att_out = out;                                       // [B,S,D]
    float* probs   = out + (size_t)M_ * D_;                     // [B,H,S,S]
    float* contrib = probs + (size_t)BH_ * S_ * S_;             // [B,H,S]

    gemm_qkv<<<dim3(79, 18), 256>>>(hs, Wq, bq, Wk, bk, Wv, bv);
    scores_kernel<<<dim3(5, 5, 192), 256>>>(probs);
    softmax_kernel<<<BH_ * S_, 256>>>(probs, mask);
    contrib_kernel<<<BH_, 256>>>(contrib);
    ctx_kernel<<<dim3(5, 192), 256>>>(probs);
    gemm_out<<<dim3(79, 6), 256>>>(Wo, bo, att_out);
}

// round 4
// speedup vs baseline: 2.3305x; 1.1180x over previous
#include <cuda_runtime.h>
#include <cstdint>

// Problem constants
#define B_   16
#define S_   626
#define D_   768
#define H_   12
#define HD_  64
#define M_   (B_*S_)          // 10016
#define BH_  (B_*H_)          // 192
#define SM1_ (S_-1)           // 625
#define PSTR 644              // P row stride (floats)
#define QSTR 68               // Q/K tile row stride (floats), full K=64 depth
#define VSTR 72               // V tile row stride

// Scratch (device globals; no cudaMalloc allowed)
__device__ float g_q[BH_*(size_t)S_*HD_];     // [b,h,s,hd]
__device__ float g_k[BH_*(size_t)S_*HD_];
__device__ float g_v[BH_*(size_t)S_*HD_];
__device__ float g_ctx[(size_t)M_*D_];        // [b,s, h*64+hd]
__device__ float g_contrib[BH_*S_];           // fixed scores col 0

// ---------------------------------------------------------------------------
// tf32 helpers
// ---------------------------------------------------------------------------
__device__ __forceinline__ uint32_t f2t(float x) {
    uint32_t r;
    asm("cvt.rna.tf32.f32 %0, %1;" : "=r"(r) : "f"(x));
    return r;
}

__device__ __forceinline__ void mma_tf32(float c[4],
    uint32_t a0, uint32_t a1, uint32_t a2, uint32_t a3,
    uint32_t b0, uint32_t b1)
{
    asm volatile(
        "mma.sync.aligned.m16n8k8.row.col.f32.tf32.tf32.f32 "
        "{%0,%1,%2,%3}, {%4,%5,%6,%7}, {%8,%9}, {%0,%1,%2,%3};"
        : "+f"(c[0]), "+f"(c[1]), "+f"(c[2]), "+f"(c[3])
        : "r"(a0), "r"(a1), "r"(a2), "r"(a3), "r"(b0), "r"(b1));
}

// ---------------------------------------------------------------------------
// Fused QKV projection (tf32 MMA): 128x128 tile, BK=16, 256 threads.
// ---------------------------------------------------------------------------
__global__ __launch_bounds__(256) void gemm_qkv(
    const float* __restrict__ X,
    const float* __restrict__ Wq, const float* __restrict__ bq,
    const float* __restrict__ Wk, const float* __restrict__ bk,
    const float* __restrict__ Wv, const float* __restrict__ bv)
{
    __shared__ uint32_t As[128][20];
    __shared__ uint32_t Bs[16][136];
    const int tid = threadIdx.x;
    const int m0  = blockIdx.x * 128;
    const int ng  = blockIdx.y * 128;
    const int mat = ng / D_;
    const int n0  = ng - mat * D_;
    const float* W    = (mat == 0) ? Wq : (mat == 1) ? Wk : Wv;
    const float* bias = (mat == 0) ? bq : (mat == 1) ? bk : bv;
    float* dst        = (mat == 0) ? g_q : (mat == 1) ? g_k : g_v;

    const int wid = tid >> 5, lane = tid & 31;
    const int gid = lane >> 2, tk = lane & 3;
    const int wm = (wid & 1) * 64;
    const int wn = (wid >> 1) * 32;

    float acc[4][4][4];
    #pragma unroll
    for (int mi = 0; mi < 4; mi++)
        #pragma unroll
        for (int ni = 0; ni < 4; ni++)
            #pragma unroll
            for (int r = 0; r < 4; r++) acc[mi][ni][r] = 0.f;

    for (int k0 = 0; k0 < D_; k0 += 16) {
        #pragma unroll
        for (int i = 0; i < 2; i++) {
            const int idx = tid + i * 256;
            const int row = idx >> 2, c4 = (idx & 3) << 2;
            float4 v = make_float4(0.f, 0.f, 0.f, 0.f);
            if (m0 + row < M_)
                v = *(const float4*)(X + (size_t)(m0 + row) * D_ + k0 + c4);
            uint4 t;
            t.x = f2t(v.x); t.y = f2t(v.y); t.z = f2t(v.z); t.w = f2t(v.w);
            *(uint4*)&As[row][c4] = t;
        }
        #pragma unroll
        for (int i = 0; i < 2; i++) {
            const int idx = tid + i * 256;
            const int kr = idx >> 5, c4 = (idx & 31) << 2;
            float4 v = *(const float4*)(W + (size_t)(k0 + kr) * D_ + n0 + c4);
            uint4 t;
            t.x = f2t(v.x); t.y = f2t(v.y); t.z = f2t(v.z); t.w = f2t(v.w);
            *(uint4*)&Bs[kr][c4] = t;
        }
        __syncthreads();
        #pragma unroll
        for (int ks = 0; ks < 16; ks += 8) {
            uint32_t bf[4][2];
            #pragma unroll
            for (int ni = 0; ni < 4; ni++) {
                bf[ni][0] = Bs[ks + tk    ][wn + ni * 8 + gid];
                bf[ni][1] = Bs[ks + tk + 4][wn + ni * 8 + gid];
            }
            #pragma unroll
            for (int mi = 0; mi < 4; mi++) {
                const int am = wm + mi * 16;
                const uint32_t a0 = As[am + gid    ][ks + tk];
                const uint32_t a1 = As[am + gid + 8][ks + tk];
                const uint32_t a2 = As[am + gid    ][ks + tk + 4];
                const uint32_t a3 = As[am + gid + 8][ks + tk + 4];
                #pragma unroll
                for (int ni = 0; ni < 4; ni++)
                    mma_tf32(acc[mi][ni], a0, a1, a2, a3, bf[ni][0], bf[ni][1]);
            }
        }
        __syncthreads();
    }

    #pragma unroll
    for (int mi = 0; mi < 4; mi++) {
        #pragma unroll
        for (int ni = 0; ni < 4; ni++) {
            const int col = n0 + wn + ni * 8 + 2 * tk;
            const int h = col >> 6, hd = col & 63;
            const float b0v = bias[col], b1v = bias[col + 1];
            const int r0 = m0 + wm + mi * 16 + gid;
            const int r1 = r0 + 8;
            if (r0 < M_) {
                const int b = r0 / S_, s = r0 - b * S_;
                *(float2*)(dst + (((size_t)(b * H_ + h)) * S_ + s) * HD_ + hd) =
                    make_float2(acc[mi][ni][0] + b0v, acc[mi][ni][1] + b1v);
            }
            if (r1 < M_) {
                const int b = r1 / S_, s = r1 - b * S_;
                *(float2*)(dst + (((size_t)(b * H_ + h)) * S_ + s) * HD_ + hd) =
                    make_float2(acc[mi][ni][2] + b0v, acc[mi][ni][3] + b1v);
            }
        }
    }
}

// ---------------------------------------------------------------------------
// Output projection (tf32 MMA): out[M,768] = g_ctx @ Wo + bo
// ---------------------------------------------------------------------------
__global__ __launch_bounds__(256) void gemm_out(
    const float* __restrict__ W, const float* __restrict__ bias,
    float* __restrict__ out)
{
    __shared__ uint32_t As[128][20];
    __shared__ uint32_t Bs[16][136];
    const int tid = threadIdx.x;
    const int m0  = blockIdx.x * 128;
    const int n0  = blockIdx.y * 128;

    const int wid = tid >> 5, lane = tid & 31;
    const int gid = lane >> 2, tk = lane & 3;
    const int wm = (wid & 1) * 64;
    const int wn = (wid >> 1) * 32;

    float acc[4][4][4];
    #pragma unroll
    for (int mi = 0; mi < 4; mi++)
        #pragma unroll
        for (int ni = 0; ni < 4; ni++)
            #pragma unroll
            for (int r = 0; r < 4; r++) acc[mi][ni][r] = 0.f;

    for (int k0 = 0; k0 < D_; k0 += 16) {
        #pragma unroll
        for (int i = 0; i < 2; i++) {
            const int idx = tid + i * 256;
            const int row = idx >> 2, c4 = (idx & 3) << 2;
            float4 v = make_float4(0.f, 0.f, 0.f, 0.f);
            if (m0 + row < M_)
                v = *(const float4*)(g_ctx + (size_t)(m0 + row) * D_ + k0 + c4);
            uint4 t;
            t.x = f2t(v.x); t.y = f2t(v.y); t.z = f2t(v.z); t.w = f2t(v.w);
            *(uint4*)&As[row][c4] = t;
        }
        #pragma unroll
        for (int i = 0; i < 2; i++) {
            const int idx = tid + i * 256;
            const int kr = idx >> 5, c4 = (idx & 31) << 2;
            float4 v = *(const float4*)(W + (size_t)(k0 + kr) * D_ + n0 + c4);
            uint4 t;
            t.x = f2t(v.x); t.y = f2t(v.y); t.z = f2t(v.z); t.w = f2t(v.w);
            *(uint4*)&Bs[kr][c4] = t;
        }
        __syncthreads();
        #pragma unroll
        for (int ks = 0; ks < 16; ks += 8) {
            uint32_t bf[4][2];
            #pragma unroll
            for (int ni = 0; ni < 4; ni++) {
                bf[ni][0] = Bs[ks + tk    ][wn + ni * 8 + gid];
                bf[ni][1] = Bs[ks + tk + 4][wn + ni * 8 + gid];
            }
            #pragma unroll
            for (int mi = 0; mi < 4; mi++) {
                const int am = wm + mi * 16;
                const uint32_t a0 = As[am + gid    ][ks + tk];
                const uint32_t a1 = As[am + gid + 8][ks + tk];
                const uint32_t a2 = As[am + gid    ][ks + tk + 4];
                const uint32_t a3 = As[am + gid + 8][ks + tk + 4];
                #pragma unroll
                for (int ni = 0; ni < 4; ni++)
                    mma_tf32(acc[mi][ni], a0, a1, a2, a3, bf[ni][0], bf[ni][1]);
            }
        }
        __syncthreads();
    }

    #pragma unroll
    for (int mi = 0; mi < 4; mi++) {
        #pragma unroll
        for (int ni = 0; ni < 4; ni++) {
            const int col = n0 + wn + ni * 8 + 2 * tk;
            const float b0v = bias[col], b1v = bias[col + 1];
            const int r0 = m0 + wm + mi * 16 + gid;
            const int r1 = r0 + 8;
            if (r0 < M_)
                *(float2*)(out + (size_t)r0 * D_ + col) =
                    make_float2(acc[mi][ni][0] + b0v, acc[mi][ni][1] + b1v);
            if (r1 < M_)
                *(float2*)(out + (size_t)r1 * D_ + col) =
                    make_float2(acc[mi][ni][2] + b0v, acc[mi][ni][3] + b1v);
        }
    }
}

// ---------------------------------------------------------------------------
// Fused attention: per (bh, 64-row q tile):
//   scores strip (64x626) -> SMEM P -> softmax (+row0 fix, contrib capture)
//   -> probs written once to gmem -> ctx = P @ V from SMEM.
// Dynamic smem: P[64][644] + Q[64][QSTR] + KV (K [64][QSTR] / V [64][VSTR]).
// ---------------------------------------------------------------------------
__global__ __launch_bounds__(256) void fused_attn(
    float* __restrict__ probs, const int* __restrict__ mask)
{
    extern __shared__ float sm[];
    float*    P  = sm;                                   // [64][PSTR]
    uint32_t* Qs = (uint32_t*)(sm + 64 * PSTR);          // [64][QSTR]
    uint32_t* KV = Qs + 64 * QSTR;                       // K [64][QSTR] / V [64][VSTR]

    const int bh  = blockIdx.y;
    const int m0  = blockIdx.x * 64;
    const int tid = threadIdx.x;
    const int wid = tid >> 5, lane = tid & 31;
    const int gid = lane >> 2, tk = lane & 3;
    const int wm  = (wid & 3) * 16;     // 4 warps along m
    const int wn  = (wid >> 2) * 32;    // 2 warps along n
    const int b   = bh / H_;
    const int h   = bh - b * H_;

    const float* qb = g_q + (size_t)bh * S_ * HD_;
    const float* kb = g_k + (size_t)bh * S_ * HD_;
    const float* vb = g_v + (size_t)bh * S_ * HD_;
    float* pgm = probs + (size_t)bh * S_ * S_;

    // zero pad columns 626..PSTR-1 (read by ctx tail chunk)
    for (int i = tid; i < 64 * (PSTR - S_); i += 256) {
        const int r = i / (PSTR - S_);
        const int c = S_ + i - r * (PSTR - S_);
        P[r * PSTR + c] = 0.f;
    }

    // load Q tile (rows m0..m0+63), full depth 64, stride QSTR
    #pragma unroll
    for (int i = 0; i < 4; i++) {
        const int idx = tid + i * 256;
        const int row = idx >> 4, c4 = (idx & 15) << 2;
        float4 v = make_float4(0.f, 0.f, 0.f, 0.f);
        if (m0 + row < S_) v = *(const float4*)(qb + (size_t)(m0 + row) * HD_ + c4);
        uint4 t;
        t.x = f2t(v.x); t.y = f2t(v.y); t.z = f2t(v.z); t.w = f2t(v.w);
        *(uint4*)&Qs[row * QSTR + c4] = t;
    }

    // ---- scores phase: P[64][626] = (Q @ K^T) * 0.125 ----
    for (int nc = 0; nc < 10; nc++) {
        const int n0 = nc * 64;
        __syncthreads();
        #pragma unroll
        for (int i = 0; i < 4; i++) {
            const int idx = tid + i * 256;
            const int row = idx >> 4, c4 = (idx & 15) << 2;
            float4 v = make_float4(0.f, 0.f, 0.f, 0.f);
            if (n0 + row < S_) v = *(const float4*)(kb + (size_t)(n0 + row) * HD_ + c4);
            uint4 t;
            t.x = f2t(v.x); t.y = f2t(v.y); t.z = f2t(v.z); t.w = f2t(v.w);
            *(uint4*)&KV[row * QSTR + c4] = t;
        }
        __syncthreads();

        float acc[4][4];
        #pragma unroll
        for (int ni = 0; ni < 4; ni++)
            #pragma unroll
            for (int r = 0; r < 4; r++) acc[ni][r] = 0.f;

        #pragma unroll
        for (int ks = 0; ks < 64; ks += 8) {
            const uint32_t a0 = Qs[(wm + gid    ) * QSTR + ks + tk];
            const uint32_t a1 = Qs[(wm + gid + 8) * QSTR + ks + tk];
            const uint32_t a2 = Qs[(wm + gid    ) * QSTR + ks + tk + 4];
            const uint32_t a3 = Qs[(wm + gid + 8) * QSTR + ks + tk + 4];
            #pragma unroll
            for (int ni = 0; ni < 4; ni++) {
                const int nb = wn + ni * 8 + gid;
                mma_tf32(acc[ni], a0, a1, a2, a3,
                         KV[nb * QSTR + ks + tk], KV[nb * QSTR + ks + tk + 4]);
            }
        }

        #pragma unroll
        for (int ni = 0; ni < 4; ni++) {
            const int col = n0 + wn + ni * 8 + 2 * tk;   // even
            if (col < S_) {
                *(float2*)&P[(wm + gid    ) * PSTR + col] =
                    make_float2(acc[ni][0] * 0.125f, acc[ni][1] * 0.125f);
                *(float2*)&P[(wm + gid + 8) * PSTR + col] =
                    make_float2(acc[ni][2] * 0.125f, acc[ni][3] * 0.125f);
            }
        }
    }
    __syncthreads();

    // ---- softmax phase: warp w owns rows w*8..w*8+7 ----
    for (int r = wid * 8; r < wid * 8 + 8; r++) {
        const int q = m0 + r;
        if (q >= S_) break;
        float* row = P + r * PSTR;

        float mx = -3.4e38f;
        for (int i = lane; i < S_; i += 32) mx = fmaxf(mx, row[i]);
        #pragma unroll
        for (int o = 16; o; o >>= 1) mx = fmaxf(mx, __shfl_xor_sync(0xffffffffu, mx, o));

        if (q == 0) {
            const float add = mx * 0.25f;
            for (int i = lane; i < S_; i += 32) {
                const int mk = (i == 0) ? 0 : mask[b * SM1_ + i - 1];
                if (mk == 0) row[i] += add;
            }
            __syncwarp();
            mx = -3.4e38f;
            for (int i = lane; i < S_; i += 32) mx = fmaxf(mx, row[i]);
            #pragma unroll
            for (int o = 16; o; o >>= 1) mx = fmaxf(mx, __shfl_xor_sync(0xffffffffu, mx, o));
        }

        if (lane == 0) g_contrib[(size_t)bh * S_ + q] = row[0];

        float s = 0.f;
        for (int i = lane; i < S_; i += 32) {
            const float e = expf(row[i] - mx);
            row[i] = e;
            s += e;
        }
        #pragma unroll
        for (int o = 16; o; o >>= 1) s += __shfl_xor_sync(0xffffffffu, s, o);
        const float inv = 1.0f / s;

        float* prow = pgm + (size_t)q * S_;
        for (int i = lane; i < S_; i += 32) {
            const float p = row[i] * inv;
            row[i] = p;          // normalized prob kept for ctx
            prow[i] = p;         // single gmem write of probs
        }
    }
    __syncthreads();

    // ---- ctx phase: ctx[64][64] = P[64][626] @ V[626][64] ----
    float cacc[4][4];
    #pragma unroll
    for (int ni = 0; ni < 4; ni++)
        #pragma unroll
        for (int r = 0; r < 4; r++) cacc[ni][r] = 0.f;

    for (int kc = 0; kc < 10; kc++) {
        const int k0 = kc * 64;
        __syncthreads();
        #pragma unroll
        for (int i = 0; i < 4; i++) {
            const int idx = tid + i * 256;
            const int row = idx >> 4, c4 = (idx & 15) << 2;
            float4 v = make_float4(0.f, 0.f, 0.f, 0.f);
            if (k0 + row < S_) v = *(const float4*)(vb + (size_t)(k0 + row) * HD_ + c4);
            uint4 t;
            t.x = f2t(v.x); t.y = f2t(v.y); t.z = f2t(v.z); t.w = f2t(v.w);
            *(uint4*)&KV[row * VSTR + c4] = t;   // V: [k][n], stride VSTR
        }
        __syncthreads();

        #pragma unroll
        for (int ks = 0; ks < 64; ks += 8) {
            const uint32_t a0 = f2t(P[(wm + gid    ) * PSTR + k0 + ks + tk]);
            const uint32_t a1 = f2t(P[(wm + gid + 8) * PSTR + k0 + ks + tk]);
            const uint32_t a2 = f2t(P[(wm + gid    ) * PSTR + k0 + ks + tk + 4]);
            const uint32_t a3 = f2t(P[(wm + gid + 8) * PSTR + k0 + ks + tk + 4]);
            #pragma unroll
            for (int ni = 0; ni < 4; ni++) {
                mma_tf32(cacc[ni], a0, a1, a2, a3,
                         KV[(ks + tk    ) * VSTR + wn + ni * 8 + gid],
                         KV[(ks + tk + 4) * VSTR + wn + ni * 8 + gid]);
            }
        }
    }

    #pragma unroll
    for (int ni = 0; ni < 4; ni++) {
        const int col = wn + ni * 8 + 2 * tk;   // 0..62
        const int r0 = m0 + wm + gid;
        const int r1 = r0 + 8;
        if (r0 < S_)
            *(float2*)(g_ctx + ((size_t)(b * S_ + r0)) * D_ + h * HD_ + col) =
                make_float2(cacc[ni][0], cacc[ni][1]);
        if (r1 < S_)
            *(float2*)(g_ctx + ((size_t)(b * S_ + r1)) * D_ + h * HD_ + col) =
                make_float2(cacc[ni][2], cacc[ni][3]);
    }
}

// ---------------------------------------------------------------------------
// Contribution: softmax over q of g_contrib[bh, :]
// ---------------------------------------------------------------------------
__global__ __launch_bounds__(256) void contrib_kernel(float* __restrict__ out)
{
    const int bh = blockIdx.x;
    const float* src = g_contrib + (size_t)bh * S_;
    __shared__ float red[8];
    const int tid = threadIdx.x;

    float m = -3.4e38f;
    for (int i = tid; i < S_; i += 256) m = fmaxf(m, src[i]);
    #pragma unroll
    for (int o = 16; o; o >>= 1) m = fmaxf(m, __shfl_xor_sync(0xffffffffu, m, o));
    if ((tid & 31) == 0) red[tid >> 5] = m;
    __syncthreads();
    if (tid == 0) {
        float mm = red[0];
        #pragma unroll
        for (int w = 1; w < 8; w++) mm = fmaxf(mm, red[w]);
        red[0] = mm;
    }
    __syncthreads();
    m = red[0];
    __syncthreads();

    float s = 0.f;
    for (int i = tid; i < S_; i += 256) s += expf(src[i] - m);
    #pragma unroll
    for (int o = 16; o; o >>= 1) s += __shfl_xor_sync(0xffffffffu, s, o);
    if ((tid & 31) == 0) red[tid >> 5] = s;
    __syncthreads();
    if (tid == 0) {
        float ss = 0.f;
        #pragma unroll
        for (int w = 0; w < 8; w++) ss += red[w];
        red[0] = ss;
    }
    __syncthreads();
    const float inv = 1.0f / red[0];
    for (int i = tid; i < S_; i += 256)
        out[(size_t)bh * S_ + i] = expf(src[i] - m) * inv;
}

// ---------------------------------------------------------------------------
// Launch
// ---------------------------------------------------------------------------
extern "C" void kernel_launch(void* const* d_in, const int* in_sizes, int n_in,
                              void* d_out, int out_size)
{
    const float* hs = (const float*)d_in[0];
    const int*  mask = (const int*) d_in[1];
    const float* Wq = (const float*)d_in[2];
    const float* bq = (const float*)d_in[3];
    const float* Wk = (const float*)d_in[4];
    const float* bk = (const float*)d_in[5];
    const float* Wv = (const float*)d_in[6];
    const float* bv = (const float*)d_in[7];
    const float* Wo = (const float*)d_in[8];
    const float* bo = (const float*)d_in[9];

    float* out     = (float*)d_out;
    float* att_out = out;                                       // [B,S,D]
    float* probs   = out + (size_t)M_ * D_;                     // [B,H,S,S]
    float* contrib = probs + (size_t)BH_ * S_ * S_;             // [B,H,S]

    // dynamic smem: P + Q + KV(max of K/V layouts)
    const int smem_bytes = (64 * PSTR + 64 * QSTR + 64 * VSTR) * 4;
    cudaFuncSetAttribute(fused_attn,
        cudaFuncAttributeMaxDynamicSharedMemorySize, smem_bytes);

    gemm_qkv<<<dim3(79, 18), 256>>>(hs, Wq, bq, Wk, bk, Wv, bv);
    fused_attn<<<dim3(10, 192), 256, smem_bytes>>>(probs, mask);
    contrib_kernel<<<BH_, 256>>>(contrib);
    gemm_out<<<dim3(79, 6), 256>>>(Wo, bo, att_out);
}

// round 5
// speedup vs baseline: 2.5005x; 1.0729x over previous
#include <cuda_runtime.h>
#include <cstdint>

// Problem constants
#define B_   16
#define S_   626
#define D_   768
#define H_   12
#define HD_  64
#define M_   (B_*S_)          // 10016
#define BH_  (B_*H_)          // 192
#define SM1_ (S_-1)           // 625
#define PSTR 644              // P row stride (floats)
#define QSTR 68               // Q/K tile row stride (floats)
#define VSTR 72               // V tile row stride
#define QT   32               // q-tile rows in fused_attn

// Scratch (device globals; no cudaMalloc allowed)
__device__ float g_q[BH_*(size_t)S_*HD_];     // [b,h,s,hd]
__device__ float g_k[BH_*(size_t)S_*HD_];
__device__ float g_v[BH_*(size_t)S_*HD_];
__device__ float g_ctx[(size_t)M_*D_];        // [b,s, h*64+hd]
__device__ float g_contrib[BH_*S_];           // fixed scores col 0

// ---------------------------------------------------------------------------
// helpers
// ---------------------------------------------------------------------------
__device__ __forceinline__ uint32_t f2t(float x) {
    uint32_t r;
    asm("cvt.rna.tf32.f32 %0, %1;" : "=r"(r) : "f"(x));
    return r;
}

__device__ __forceinline__ void mma_tf32(float c[4],
    uint32_t a0, uint32_t a1, uint32_t a2, uint32_t a3,
    uint32_t b0, uint32_t b1)
{
    asm volatile(
        "mma.sync.aligned.m16n8k8.row.col.f32.tf32.tf32.f32 "
        "{%0,%1,%2,%3}, {%4,%5,%6,%7}, {%8,%9}, {%0,%1,%2,%3};"
        : "+f"(c[0]), "+f"(c[1]), "+f"(c[2]), "+f"(c[3])
        : "r"(a0), "r"(a1), "r"(a2), "r"(a3), "r"(b0), "r"(b1));
}

__device__ __forceinline__ void cp16(void* smem, const void* gmem) {
    uint32_t s = (uint32_t)__cvta_generic_to_shared(smem);
    asm volatile("cp.async.ca.shared.global [%0], [%1], 16;" :: "r"(s), "l"(gmem));
}
__device__ __forceinline__ void cp_commit() {
    asm volatile("cp.async.commit_group;");
}

// ---------------------------------------------------------------------------
// Fused QKV projection (tf32 MMA, cp.async double-buffered): 128x128, BK=16.
// ---------------------------------------------------------------------------
__global__ __launch_bounds__(256) void gemm_qkv(
    const float* __restrict__ X,
    const float* __restrict__ Wq, const float* __restrict__ bq,
    const float* __restrict__ Wk, const float* __restrict__ bk,
    const float* __restrict__ Wv, const float* __restrict__ bv)
{
    __shared__ float As[2][128][20];
    __shared__ float Bs[2][16][136];
    const int tid = threadIdx.x;
    const int m0  = blockIdx.x * 128;
    const int ng  = blockIdx.y * 128;
    const int mat = ng / D_;
    const int n0  = ng - mat * D_;
    const float* W    = (mat == 0) ? Wq : (mat == 1) ? Wk : Wv;
    const float* bias = (mat == 0) ? bq : (mat == 1) ? bk : bv;
    float* dst        = (mat == 0) ? g_q : (mat == 1) ? g_k : g_v;

    const int wid = tid >> 5, lane = tid & 31;
    const int gid = lane >> 2, tk = lane & 3;
    const int wm = (wid & 1) * 64;
    const int wn = (wid >> 1) * 32;

    const int arow = tid >> 1, ac4 = (tid & 1) * 8;   // 2 float4 each -> 128x16
    const int brow = tid >> 5, bc4 = (tid & 31) * 4;  // pairs below

    float acc[4][4][4];
    #pragma unroll
    for (int mi = 0; mi < 4; mi++)
        #pragma unroll
        for (int ni = 0; ni < 4; ni++)
            #pragma unroll
            for (int r = 0; r < 4; r++) acc[mi][ni][r] = 0.f;

    const bool aval = (m0 + arow < M_);
    const float zero4[4] = {0.f, 0.f, 0.f, 0.f};

    // stage loader
    auto load_stage = [&](int st, int k0) {
        // A: each thread does rows arow, cols ac4..ac4+7 (2 cp16)
        if (aval) {
            cp16(&As[st][arow][ac4],     X + (size_t)(m0 + arow) * D_ + k0 + ac4);
            cp16(&As[st][arow][ac4 + 4], X + (size_t)(m0 + arow) * D_ + k0 + ac4 + 4);
        } else {
            *(float4*)&As[st][arow][ac4]     = *(const float4*)zero4;
            *(float4*)&As[st][arow][ac4 + 4] = *(const float4*)zero4;
        }
        // B: 16x128 floats = 512 float4; 256 threads -> 2 each
        cp16(&Bs[st][brow][bc4],     W + (size_t)(k0 + brow) * D_ + n0 + bc4);
        cp16(&Bs[st][brow + 8][bc4], W + (size_t)(k0 + brow + 8) * D_ + n0 + bc4);
    };

    load_stage(0, 0);
    cp_commit();

    const int NK = D_ / 16;   // 48
    for (int kt = 0; kt < NK; kt++) {
        const int cur = kt & 1;
        if (kt + 1 < NK) {
            load_stage(cur ^ 1, (kt + 1) * 16);
            cp_commit();
            asm volatile("cp.async.wait_group 1;");
        } else {
            asm volatile("cp.async.wait_group 0;");
        }
        __syncthreads();

        #pragma unroll
        for (int ks = 0; ks < 16; ks += 8) {
            uint32_t bf[4][2];
            #pragma unroll
            for (int ni = 0; ni < 4; ni++) {
                bf[ni][0] = f2t(Bs[cur][ks + tk    ][wn + ni * 8 + gid]);
                bf[ni][1] = f2t(Bs[cur][ks + tk + 4][wn + ni * 8 + gid]);
            }
            #pragma unroll
            for (int mi = 0; mi < 4; mi++) {
                const int am = wm + mi * 16;
                const uint32_t a0 = f2t(As[cur][am + gid    ][ks + tk]);
                const uint32_t a1 = f2t(As[cur][am + gid + 8][ks + tk]);
                const uint32_t a2 = f2t(As[cur][am + gid    ][ks + tk + 4]);
                const uint32_t a3 = f2t(As[cur][am + gid + 8][ks + tk + 4]);
                #pragma unroll
                for (int ni = 0; ni < 4; ni++)
                    mma_tf32(acc[mi][ni], a0, a1, a2, a3, bf[ni][0], bf[ni][1]);
            }
        }
        __syncthreads();
    }

    #pragma unroll
    for (int mi = 0; mi < 4; mi++) {
        #pragma unroll
        for (int ni = 0; ni < 4; ni++) {
            const int col = n0 + wn + ni * 8 + 2 * tk;
            const int h = col >> 6, hd = col & 63;
            const float b0v = bias[col], b1v = bias[col + 1];
            const int r0 = m0 + wm + mi * 16 + gid;
            const int r1 = r0 + 8;
            if (r0 < M_) {
                const int b = r0 / S_, s = r0 - b * S_;
                *(float2*)(dst + (((size_t)(b * H_ + h)) * S_ + s) * HD_ + hd) =
                    make_float2(acc[mi][ni][0] + b0v, acc[mi][ni][1] + b1v);
            }
            if (r1 < M_) {
                const int b = r1 / S_, s = r1 - b * S_;
                *(float2*)(dst + (((size_t)(b * H_ + h)) * S_ + s) * HD_ + hd) =
                    make_float2(acc[mi][ni][2] + b0v, acc[mi][ni][3] + b1v);
            }
        }
    }
}

// ---------------------------------------------------------------------------
// Output projection (tf32 MMA, cp.async double-buffered)
// ---------------------------------------------------------------------------
__global__ __launch_bounds__(256) void gemm_out(
    const float* __restrict__ W, const float* __restrict__ bias,
    float* __restrict__ out)
{
    __shared__ float As[2][128][20];
    __shared__ float Bs[2][16][136];
    const int tid = threadIdx.x;
    const int m0  = blockIdx.x * 128;
    const int n0  = blockIdx.y * 128;

    const int wid = tid >> 5, lane = tid & 31;
    const int gid = lane >> 2, tk = lane & 3;
    const int wm = (wid & 1) * 64;
    const int wn = (wid >> 1) * 32;

    const int arow = tid >> 1, ac4 = (tid & 1) * 8;
    const int brow = tid >> 5, bc4 = (tid & 31) * 4;

    float acc[4][4][4];
    #pragma unroll
    for (int mi = 0; mi < 4; mi++)
        #pragma unroll
        for (int ni = 0; ni < 4; ni++)
            #pragma unroll
            for (int r = 0; r < 4; r++) acc[mi][ni][r] = 0.f;

    const bool aval = (m0 + arow < M_);
    const float zero4[4] = {0.f, 0.f, 0.f, 0.f};

    auto load_stage = [&](int st, int k0) {
        if (aval) {
            cp16(&As[st][arow][ac4],     g_ctx + (size_t)(m0 + arow) * D_ + k0 + ac4);
            cp16(&As[st][arow][ac4 + 4], g_ctx + (size_t)(m0 + arow) * D_ + k0 + ac4 + 4);
        } else {
            *(float4*)&As[st][arow][ac4]     = *(const float4*)zero4;
            *(float4*)&As[st][arow][ac4 + 4] = *(const float4*)zero4;
        }
        cp16(&Bs[st][brow][bc4],     W + (size_t)(k0 + brow) * D_ + n0 + bc4);
        cp16(&Bs[st][brow + 8][bc4], W + (size_t)(k0 + brow + 8) * D_ + n0 + bc4);
    };

    load_stage(0, 0);
    cp_commit();

    const int NK = D_ / 16;
    for (int kt = 0; kt < NK; kt++) {
        const int cur = kt & 1;
        if (kt + 1 < NK) {
            load_stage(cur ^ 1, (kt + 1) * 16);
            cp_commit();
            asm volatile("cp.async.wait_group 1;");
        } else {
            asm volatile("cp.async.wait_group 0;");
        }
        __syncthreads();

        #pragma unroll
        for (int ks = 0; ks < 16; ks += 8) {
            uint32_t bf[4][2];
            #pragma unroll
            for (int ni = 0; ni < 4; ni++) {
                bf[ni][0] = f2t(Bs[cur][ks + tk    ][wn + ni * 8 + gid]);
                bf[ni][1] = f2t(Bs[cur][ks + tk + 4][wn + ni * 8 + gid]);
            }
            #pragma unroll
            for (int mi = 0; mi < 4; mi++) {
                const int am = wm + mi * 16;
                const uint32_t a0 = f2t(As[cur][am + gid    ][ks + tk]);
                const uint32_t a1 = f2t(As[cur][am + gid + 8][ks + tk]);
                const uint32_t a2 = f2t(As[cur][am + gid    ][ks + tk + 4]);
                const uint32_t a3 = f2t(As[cur][am + gid + 8][ks + tk + 4]);
                #pragma unroll
                for (int ni = 0; ni < 4; ni++)
                    mma_tf32(acc[mi][ni], a0, a1, a2, a3, bf[ni][0], bf[ni][1]);
            }
        }
        __syncthreads();
    }

    #pragma unroll
    for (int mi = 0; mi < 4; mi++) {
        #pragma unroll
        for (int ni = 0; ni < 4; ni++) {
            const int col = n0 + wn + ni * 8 + 2 * tk;
            const float b0v = bias[col], b1v = bias[col + 1];
            const int r0 = m0 + wm + mi * 16 + gid;
            const int r1 = r0 + 8;
            if (r0 < M_)
                *(float2*)(out + (size_t)r0 * D_ + col) =
                    make_float2(acc[mi][ni][0] + b0v, acc[mi][ni][1] + b1v);
            if (r1 < M_)
                *(float2*)(out + (size_t)r1 * D_ + col) =
                    make_float2(acc[mi][ni][2] + b0v, acc[mi][ni][3] + b1v);
        }
    }
}

// ---------------------------------------------------------------------------
// Fused attention, 32-row q tile (2 blocks/SM):
//   scores strip (32x626) -> SMEM P -> softmax (+row0 fix, contrib capture)
//   -> probs written once -> ctx = P @ V from SMEM.
// ---------------------------------------------------------------------------
__global__ __launch_bounds__(256) void fused_attn(
    float* __restrict__ probs, const int* __restrict__ mask)
{
    extern __shared__ float sm[];
    float*    P  = sm;                                   // [QT][PSTR]
    uint32_t* Qs = (uint32_t*)(sm + QT * PSTR);          // [QT][QSTR]
    uint32_t* KV = Qs + QT * QSTR;                       // K [64][QSTR] / V [64][VSTR]

    const int bh  = blockIdx.y;
    const int m0  = blockIdx.x * QT;
    const int tid = threadIdx.x;
    const int wid = tid >> 5, lane = tid & 31;
    const int gid = lane >> 2, tk = lane & 3;
    const int wm  = (wid & 1) * 16;     // 2 warps along m (16 rows each)
    const int wn  = (wid >> 1) * 16;    // 4 warps along n (16 cols each)
    const int b   = bh / H_;
    const int h   = bh - b * H_;

    const float* qb = g_q + (size_t)bh * S_ * HD_;
    const float* kb = g_k + (size_t)bh * S_ * HD_;
    const float* vb = g_v + (size_t)bh * S_ * HD_;
    float* pgm = probs + (size_t)bh * S_ * S_;

    // zero pad columns 626..PSTR-1
    for (int i = tid; i < QT * (PSTR - S_); i += 256) {
        const int r = i / (PSTR - S_);
        const int c = S_ + i - r * (PSTR - S_);
        P[r * PSTR + c] = 0.f;
    }

    // load Q tile (QT rows x 64)
    #pragma unroll
    for (int i = 0; i < 2; i++) {
        const int idx = tid + i * 256;
        const int row = idx >> 4, c4 = (idx & 15) << 2;
        float4 v = make_float4(0.f, 0.f, 0.f, 0.f);
        if (m0 + row < S_) v = *(const float4*)(qb + (size_t)(m0 + row) * HD_ + c4);
        uint4 t;
        t.x = f2t(v.x); t.y = f2t(v.y); t.z = f2t(v.z); t.w = f2t(v.w);
        *(uint4*)&Qs[row * QSTR + c4] = t;
    }

    // ---- scores phase: P[QT][626] = (Q @ K^T) * 0.125 ----
    for (int nc = 0; nc < 10; nc++) {
        const int n0 = nc * 64;
        __syncthreads();
        #pragma unroll
        for (int i = 0; i < 4; i++) {
            const int idx = tid + i * 256;
            const int row = idx >> 4, c4 = (idx & 15) << 2;
            float4 v = make_float4(0.f, 0.f, 0.f, 0.f);
            if (n0 + row < S_) v = *(const float4*)(kb + (size_t)(n0 + row) * HD_ + c4);
            uint4 t;
            t.x = f2t(v.x); t.y = f2t(v.y); t.z = f2t(v.z); t.w = f2t(v.w);
            *(uint4*)&KV[row * QSTR + c4] = t;
        }
        __syncthreads();

        float acc[2][4];
        #pragma unroll
        for (int ni = 0; ni < 2; ni++)
            #pragma unroll
            for (int r = 0; r < 4; r++) acc[ni][r] = 0.f;

        #pragma unroll
        for (int ks = 0; ks < 64; ks += 8) {
            const uint32_t a0 = Qs[(wm + gid    ) * QSTR + ks + tk];
            const uint32_t a1 = Qs[(wm + gid + 8) * QSTR + ks + tk];
            const uint32_t a2 = Qs[(wm + gid    ) * QSTR + ks + tk + 4];
            const uint32_t a3 = Qs[(wm + gid + 8) * QSTR + ks + tk + 4];
            #pragma unroll
            for (int ni = 0; ni < 2; ni++) {
                const int nb = wn + ni * 8 + gid;
                mma_tf32(acc[ni], a0, a1, a2, a3,
                         KV[nb * QSTR + ks + tk], KV[nb * QSTR + ks + tk + 4]);
            }
        }

        #pragma unroll
        for (int ni = 0; ni < 2; ni++) {
            const int col = n0 + wn + ni * 8 + 2 * tk;   // even
            if (col < S_) {
                *(float2*)&P[(wm + gid    ) * PSTR + col] =
                    make_float2(acc[ni][0] * 0.125f, acc[ni][1] * 0.125f);
                *(float2*)&P[(wm + gid + 8) * PSTR + col] =
                    make_float2(acc[ni][2] * 0.125f, acc[ni][3] * 0.125f);
            }
        }
    }
    __syncthreads();

    // ---- softmax phase: warp w owns rows w*4..w*4+3 ----
    for (int r = wid * 4; r < wid * 4 + 4; r++) {
        const int q = m0 + r;
        if (q >= S_) break;
        float* row = P + r * PSTR;

        float mx = -3.4e38f;
        for (int i = lane; i < S_; i += 32) mx = fmaxf(mx, row[i]);
        #pragma unroll
        for (int o = 16; o; o >>= 1) mx = fmaxf(mx, __shfl_xor_sync(0xffffffffu, mx, o));

        if (q == 0) {
            const float add = mx * 0.25f;
            for (int i = lane; i < S_; i += 32) {
                const int mk = (i == 0) ? 0 : mask[b * SM1_ + i - 1];
                if (mk == 0) row[i] += add;
            }
            __syncwarp();
            mx = -3.4e38f;
            for (int i = lane; i < S_; i += 32) mx = fmaxf(mx, row[i]);
            #pragma unroll
            for (int o = 16; o; o >>= 1) mx = fmaxf(mx, __shfl_xor_sync(0xffffffffu, mx, o));
        }

        if (lane == 0) g_contrib[(size_t)bh * S_ + q] = row[0];

        float s = 0.f;
        for (int i = lane; i < S_; i += 32) {
            const float e = expf(row[i] - mx);
            row[i] = e;
            s += e;
        }
        #pragma unroll
        for (int o = 16; o; o >>= 1) s += __shfl_xor_sync(0xffffffffu, s, o);
        const float inv = 1.0f / s;

        float* prow = pgm + (size_t)q * S_;
        for (int i = lane; i < S_; i += 32) {
            const float p = row[i] * inv;
            row[i] = p;
            prow[i] = p;
        }
    }
    __syncthreads();

    // ---- ctx phase: ctx[QT][64] = P[QT][626] @ V[626][64] ----
    float cacc[2][4];
    #pragma unroll
    for (int ni = 0; ni < 2; ni++)
        #pragma unroll
        for (int r = 0; r < 4; r++) cacc[ni][r] = 0.f;

    for (int kc = 0; kc < 10; kc++) {
        const int k0 = kc * 64;
        __syncthreads();
        #pragma unroll
        for (int i = 0; i < 4; i++) {
            const int idx = tid + i * 256;
            const int row = idx >> 4, c4 = (idx & 15) << 2;
            float4 v = make_float4(0.f, 0.f, 0.f, 0.f);
            if (k0 + row < S_) v = *(const float4*)(vb + (size_t)(k0 + row) * HD_ + c4);
            uint4 t;
            t.x = f2t(v.x); t.y = f2t(v.y); t.z = f2t(v.z); t.w = f2t(v.w);
            *(uint4*)&KV[row * VSTR + c4] = t;
        }
        __syncthreads();

        #pragma unroll
        for (int ks = 0; ks < 64; ks += 8) {
            const uint32_t a0 = f2t(P[(wm + gid    ) * PSTR + k0 + ks + tk]);
            const uint32_t a1 = f2t(P[(wm + gid + 8) * PSTR + k0 + ks + tk]);
            const uint32_t a2 = f2t(P[(wm + gid    ) * PSTR + k0 + ks + tk + 4]);
            const uint32_t a3 = f2t(P[(wm + gid + 8) * PSTR + k0 + ks + tk + 4]);
            #pragma unroll
            for (int ni = 0; ni < 2; ni++) {
                mma_tf32(cacc[ni], a0, a1, a2, a3,
                         KV[(ks + tk    ) * VSTR + wn + ni * 8 + gid],
                         KV[(ks + tk + 4) * VSTR + wn + ni * 8 + gid]);
            }
        }
    }

    #pragma unroll
    for (int ni = 0; ni < 2; ni++) {
        const int col = wn + ni * 8 + 2 * tk;   // 0..62
        const int r0 = m0 + wm + gid;
        const int r1 = r0 + 8;
        if (r0 < S_)
            *(float2*)(g_ctx + ((size_t)(b * S_ + r0)) * D_ + h * HD_ + col) =
                make_float2(cacc[ni][0], cacc[ni][1]);
        if (r1 < S_)
            *(float2*)(g_ctx + ((size_t)(b * S_ + r1)) * D_ + h * HD_ + col) =
                make_float2(cacc[ni][2], cacc[ni][3]);
    }
}

// ---------------------------------------------------------------------------
// Contribution: softmax over q of g_contrib[bh, :]
// ---------------------------------------------------------------------------
__global__ __launch_bounds__(256) void contrib_kernel(float* __restrict__ out)
{
    const int bh = blockIdx.x;
    const float* src = g_contrib + (size_t)bh * S_;
    __shared__ float red[8];
    const int tid = threadIdx.x;

    float m = -3.4e38f;
    for (int i = tid; i < S_; i += 256) m = fmaxf(m, src[i]);
    #pragma unroll
    for (int o = 16; o; o >>= 1) m = fmaxf(m, __shfl_xor_sync(0xffffffffu, m, o));
    if ((tid & 31) == 0) red[tid >> 5] = m;
    __syncthreads();
    if (tid == 0) {
        float mm = red[0];
        #pragma unroll
        for (int w = 1; w < 8; w++) mm = fmaxf(mm, red[w]);
        red[0] = mm;
    }
    __syncthreads();
    m = red[0];
    __syncthreads();

    float s = 0.f;
    for (int i = tid; i < S_; i += 256) s += expf(src[i] - m);
    #pragma unroll
    for (int o = 16; o; o >>= 1) s += __shfl_xor_sync(0xffffffffu, s, o);
    if ((tid & 31) == 0) red[tid >> 5] = s;
    __syncthreads();
    if (tid == 0) {
        float ss = 0.f;
        #pragma unroll
        for (int w = 0; w < 8; w++) ss += red[w];
        red[0] = ss;
    }
    __syncthreads();
    const float inv = 1.0f / red[0];
    for (int i = tid; i < S_; i += 256)
        out[(size_t)bh * S_ + i] = expf(src[i] - m) * inv;
}

// ---------------------------------------------------------------------------
// Launch
// ---------------------------------------------------------------------------
extern "C" void kernel_launch(void* const* d_in, const int* in_sizes, int n_in,
                              void* d_out, int out_size)
{
    const float* hs = (const float*)d_in[0];
    const int*  mask = (const int*) d_in[1];
    const float* Wq = (const float*)d_in[2];
    const float* bq = (const float*)d_in[3];
    const float* Wk = (const float*)d_in[4];
    const float* bk = (const float*)d_in[5];
    const float* Wv = (const float*)d_in[6];
    const float* bv = (const float*)d_in[7];
    const float* Wo = (const float*)d_in[8];
    const float* bo = (const float*)d_in[9];

    float* out     = (float*)d_out;
    float* att_out = out;                                       // [B,S,D]
    float* probs   = out + (size_t)M_ * D_;                     // [B,H,S,S]
    float* contrib = probs + (size_t)BH_ * S_ * S_;             // [B,H,S]

    const int smem_bytes = (QT * PSTR + QT * QSTR + 64 * VSTR) * 4;
    cudaFuncSetAttribute(fused_attn,
        cudaFuncAttributeMaxDynamicSharedMemorySize, smem_bytes);

    gemm_qkv<<<dim3(79, 18), 256>>>(hs, Wq, bq, Wk, bk, Wv, bv);
    fused_attn<<<dim3(20, 192), 256, smem_bytes>>>(probs, mask);
    contrib_kernel<<<BH_, 256>>>(contrib);
    gemm_out<<<dim3(79, 6), 256>>>(Wo, bo, att_out);
}